// round 10
// baseline (speedup 1.0000x reference)
#include <cuda_runtime.h>
#include <cuda_bf16.h>
#include <cstdint>

// Problem constants (fixed by the dataset)
#define MAX_N 50000
#define MAX_E 800000
#define MAX_F 128

// ---------------- scratch (static device globals) ----------------
__device__ __align__(16) float g_deg [MAX_N];
__device__ __align__(16) float g_dinv[MAX_N];
__device__ __align__(16) int   g_src [MAX_E];
__device__ __align__(16) int   g_dst [MAX_E];
__device__ __align__(16) float g_norm[MAX_E];
__device__ __align__(16) int   g_rowptr[MAX_N + 1];
__device__ __align__(16) int   g_cursor[MAX_N];
__device__ __align__(16) int2  g_csr [MAX_E];     // .x = src, .y = bits(norm)
__device__ __align__(16) float g_h   [(size_t)MAX_N * MAX_F];
__device__ __align__(16) float g_agg [(size_t)MAX_N * MAX_F];
__device__ int g_is64;

// ---------------- dtype detection: int64 vs int32 edge_index ----------------
__global__ void k_detect(const int* __restrict__ ei32) {
    if (threadIdx.x || blockIdx.x) return;
    int is64 = 1;
    #pragma unroll 1
    for (int i = 0; i < 128; i++) {
        if (ei32[2 * i + 1] != 0) { is64 = 0; break; }
    }
    g_is64 = is64;
}

__device__ __forceinline__ int edge_id(const void* ei, size_t pos) {
    if (g_is64) return (int)((const long long*)ei)[pos];
    return ((const int*)ei)[pos];
}

// ---------------- degree / norm precompute ----------------
__global__ void k_zero_deg(int n) {
    int i = blockIdx.x * blockDim.x + threadIdx.x;
    if (i < n) g_deg[i] = 0.0f;
}

__global__ void k_count_deg(const void* __restrict__ ei, int E) {
    int e = blockIdx.x * blockDim.x + threadIdx.x;
    if (e < E) atomicAdd(&g_deg[edge_id(ei, (size_t)E + e)], 1.0f);
}

__global__ void k_dinv(int n) {
    int i = blockIdx.x * blockDim.x + threadIdx.x;
    if (i < n) g_dinv[i] = rsqrtf(g_deg[i] + 1.0f);
}

__global__ void k_prep_edges(const void* __restrict__ ei, int E) {
    int e = blockIdx.x * blockDim.x + threadIdx.x;
    if (e >= E) return;
    int s = edge_id(ei, e);
    int d = edge_id(ei, (size_t)E + e);
    g_src[e] = s;
    g_dst[e] = d;
    g_norm[e] = g_dinv[s] * g_dinv[d];
}

// ---------------- exclusive prefix scan of degrees -> row_ptr (single block) ----------------
__global__ __launch_bounds__(1024) void k_scan(int Nn) {
    __shared__ int warp_sums[32];
    __shared__ int carry_sh;
    int tid  = threadIdx.x;
    int lane = tid & 31;
    int wid  = tid >> 5;
    if (tid == 0) carry_sh = 0;
    __syncthreads();
    for (int base = 0; base < Nn; base += 1024) {
        int i = base + tid;
        int v = (i < Nn) ? (int)g_deg[i] : 0;
        int s = v;
        #pragma unroll
        for (int o = 1; o < 32; o <<= 1) {
            int t = __shfl_up_sync(0xFFFFFFFFu, s, o);
            if (lane >= o) s += t;
        }
        if (lane == 31) warp_sums[wid] = s;
        __syncthreads();
        if (wid == 0) {
            int ws = warp_sums[lane];
            #pragma unroll
            for (int o = 1; o < 32; o <<= 1) {
                int t = __shfl_up_sync(0xFFFFFFFFu, ws, o);
                if (lane >= o) ws += t;
            }
            warp_sums[lane] = ws;   // inclusive over warps
        }
        __syncthreads();
        int warp_off = (wid == 0) ? 0 : warp_sums[wid - 1];
        int excl = carry_sh + warp_off + (s - v);
        if (i < Nn) { g_rowptr[i] = excl; g_cursor[i] = excl; }
        __syncthreads();
        if (tid == 0) carry_sh += warp_sums[31];
        __syncthreads();
    }
    if (tid == 0) g_rowptr[Nn] = carry_sh;
}

// ---------------- CSR fill: counting-sort edges by dst ----------------
__global__ void k_fill(int E) {
    int e = blockIdx.x * blockDim.x + threadIdx.x;
    if (e >= E) return;
    int pos = atomicAdd(&g_cursor[g_dst[e]], 1);
    int2 m;
    m.x = g_src[e];
    m.y = __float_as_int(g_norm[e]);
    g_csr[pos] = m;
}

// ---------------- GEMM: g_h[M,N] = act(A[M,K]) @ W[K,N] ----------------
// Tile 128 x TN, 256 threads, micro 8 x MN. GTK=16. K%16==0, N%TN==0.
// aSel: 0 -> A = Ax (param, no relu), 1 -> A = g_agg with relu on read.
#define GTM 128
#define GTK 16

template<int TN, int MN>
__global__ __launch_bounds__(256) void k_gemm_t(const float* __restrict__ Ax,
                                                const float* __restrict__ W,
                                                int M, int K, int N, int aSel) {
    __shared__ float As[GTK][GTM + 4];     // row = 132 floats = 528 B (16B-aligned)
    __shared__ float Bs[GTK][TN + 4];
    const float* A = aSel ? (const float*)g_agg : Ax;
    int tx = threadIdx.x;            // 0..15 -> n (MN cols each)
    int ty = threadIdx.y;            // 0..15 -> m (8 rows each)
    int tid = ty * 16 + tx;
    int row0 = blockIdx.y * GTM;
    int col0 = blockIdx.x * TN;
    int K4 = K >> 2;

    float acc[8][MN] = {};
    for (int k0 = 0; k0 < K; k0 += GTK) {
        // A tile: 128 rows x 16 k = 512 float4; 2 per thread
        #pragma unroll
        for (int i = 0; i < 2; i++) {
            int q  = tid * 2 + i;        // 0..511
            int m  = q >> 2;             // row in tile
            int kq = q & 3;              // which float4 along k
            int gm = row0 + m;
            float4 v = make_float4(0.f, 0.f, 0.f, 0.f);
            if (gm < M) v = ((const float4*)A)[(size_t)gm * K4 + (k0 >> 2) + kq];
            if (aSel) {
                v.x = fmaxf(v.x, 0.f); v.y = fmaxf(v.y, 0.f);
                v.z = fmaxf(v.z, 0.f); v.w = fmaxf(v.w, 0.f);
            }
            As[kq * 4 + 0][m] = v.x;
            As[kq * 4 + 1][m] = v.y;
            As[kq * 4 + 2][m] = v.z;
            As[kq * 4 + 3][m] = v.w;
        }
        // W tile: 16 k x TN n = 4*TN float4; TN/64 per thread
        #pragma unroll
        for (int i = 0; i < TN / 64; i++) {
            int q  = tid * (TN / 64) + i;    // 0 .. 4*TN-1
            int k  = q / (TN / 4);
            int nq = q % (TN / 4);
            float4 v = ((const float4*)W)[(size_t)(k0 + k) * (N >> 2) + (col0 >> 2) + nq];
            *(float4*)&Bs[k][nq * 4] = v;
        }
        __syncthreads();
        #pragma unroll
        for (int k = 0; k < GTK; k++) {
            // vectorized, conflict-free LDS.128 operand reads
            float4 a0 = *(const float4*)&As[k][ty * 8 + 0];
            float4 a1 = *(const float4*)&As[k][ty * 8 + 4];
            float a[8] = {a0.x, a0.y, a0.z, a0.w, a1.x, a1.y, a1.z, a1.w};
            float b[MN];
            #pragma unroll
            for (int j0 = 0; j0 < MN; j0 += 4) {
                float4 bv = *(const float4*)&Bs[k][tx * MN + j0];
                b[j0 + 0] = bv.x; b[j0 + 1] = bv.y; b[j0 + 2] = bv.z; b[j0 + 3] = bv.w;
            }
            #pragma unroll
            for (int i = 0; i < 8; i++)
                #pragma unroll
                for (int j = 0; j < MN; j++)
                    acc[i][j] = fmaf(a[i], b[j], acc[i][j]);
        }
        __syncthreads();
    }
    #pragma unroll
    for (int i = 0; i < 8; i++) {
        int gm = row0 + ty * 8 + i;
        if (gm >= M) continue;
        #pragma unroll
        for (int j0 = 0; j0 < MN; j0 += 4) {
            float4 v = make_float4(acc[i][j0], acc[i][j0 + 1], acc[i][j0 + 2], acc[i][j0 + 3]);
            ((float4*)g_h)[((size_t)gm * N + col0 + tx * MN + j0) >> 2] = v;
        }
    }
}

// ---------------- CSR gather: dst[n,f] = b[f] + h[n,f]*dinv[n]^2 + sum_e h[src]*norm ----------------
// One thread per (node, float4-chunk). For F=128 a warp covers exactly one node.
__global__ void k_gather(const float4* __restrict__ bias, float4* __restrict__ outp,
                         int toOut, int total /* Nn*F4 */, int F4mask, int lg) {
    int t = blockIdx.x * blockDim.x + threadIdx.x;
    if (t >= total) return;
    int node = t >> lg;
    int f = t & F4mask;
    const float4* h4 = (const float4*)g_h;
    float d = g_dinv[node];
    float s0 = d * d;
    float4 acc = bias[f];
    float4 v = h4[((size_t)node << lg) + f];
    acc.x = fmaf(v.x, s0, acc.x);
    acc.y = fmaf(v.y, s0, acc.y);
    acc.z = fmaf(v.z, s0, acc.z);
    acc.w = fmaf(v.w, s0, acc.w);

    int p   = g_rowptr[node];
    int end = g_rowptr[node + 1];
    // unrolled by 4 for memory-level parallelism
    for (; p + 3 < end; p += 4) {
        int2 m0 = g_csr[p];
        int2 m1 = g_csr[p + 1];
        int2 m2 = g_csr[p + 2];
        int2 m3 = g_csr[p + 3];
        float4 v0 = h4[((size_t)m0.x << lg) + f];
        float4 v1 = h4[((size_t)m1.x << lg) + f];
        float4 v2 = h4[((size_t)m2.x << lg) + f];
        float4 v3 = h4[((size_t)m3.x << lg) + f];
        float s1 = __int_as_float(m0.y);
        float s2 = __int_as_float(m1.y);
        float s3 = __int_as_float(m2.y);
        float s4 = __int_as_float(m3.y);
        acc.x = fmaf(v0.x, s1, acc.x); acc.y = fmaf(v0.y, s1, acc.y);
        acc.z = fmaf(v0.z, s1, acc.z); acc.w = fmaf(v0.w, s1, acc.w);
        acc.x = fmaf(v1.x, s2, acc.x); acc.y = fmaf(v1.y, s2, acc.y);
        acc.z = fmaf(v1.z, s2, acc.z); acc.w = fmaf(v1.w, s2, acc.w);
        acc.x = fmaf(v2.x, s3, acc.x); acc.y = fmaf(v2.y, s3, acc.y);
        acc.z = fmaf(v2.z, s3, acc.z); acc.w = fmaf(v2.w, s3, acc.w);
        acc.x = fmaf(v3.x, s4, acc.x); acc.y = fmaf(v3.y, s4, acc.y);
        acc.z = fmaf(v3.z, s4, acc.z); acc.w = fmaf(v3.w, s4, acc.w);
    }
    for (; p < end; p++) {
        int2 m0 = g_csr[p];
        float s1 = __int_as_float(m0.y);
        float4 v0 = h4[((size_t)m0.x << lg) + f];
        acc.x = fmaf(v0.x, s1, acc.x); acc.y = fmaf(v0.y, s1, acc.y);
        acc.z = fmaf(v0.z, s1, acc.z); acc.w = fmaf(v0.w, s1, acc.w);
    }
    float4* dst = toOut ? outp : (float4*)g_agg;
    dst[t] = acc;
}

// ---------------- host launch ----------------
static inline int cdiv(long long a, int b) { return (int)((a + b - 1) / b); }

extern "C" void kernel_launch(void* const* d_in, const int* in_sizes, int n_in,
                              void* d_out, int out_size) {
    const float* x  = (const float*)d_in[0];
    const void*  ei = d_in[1];                 // int32 OR int64 — detected on device
    const float* W0 = (const float*)d_in[2];
    const float* b0 = (const float*)d_in[3];
    const float* W1 = (const float*)d_in[4];
    const float* b1 = (const float*)d_in[5];
    const float* W2 = (const float*)d_in[6];
    const float* b2 = (const float*)d_in[7];
    float* out = (float*)d_out;

    int F1 = in_sizes[3];              // 128
    int F0 = in_sizes[2] / F1;         // 256
    int F2 = in_sizes[5];              // 128
    int F3 = in_sizes[7];              // 64
    int Nn = in_sizes[0] / F0;         // 50000
    int E  = in_sizes[1] / 2;          // 800000

    // 0) dtype detect; degrees; norms; edge precompute; CSR build
    k_detect    <<<1, 32>>>((const int*)ei);
    k_zero_deg  <<<cdiv(Nn, 256), 256>>>(Nn);
    k_count_deg <<<cdiv(E, 256), 256>>>(ei, E);
    k_dinv      <<<cdiv(Nn, 256), 256>>>(Nn);
    k_prep_edges<<<cdiv(E, 256), 256>>>(ei, E);
    k_scan      <<<1, 1024>>>(Nn);
    k_fill      <<<cdiv(E, 256), 256>>>(E);

    dim3 tb(16, 16);

    // ---------- layer 1: x[Nn,F0] @ W0 -> F1 in g_h; gather -> g_agg ----------
    {
        int F4 = F1 / 4, lg = (F4 == 32) ? 5 : 4;
        dim3 grid(F1 / 128, cdiv(Nn, GTM));
        k_gemm_t<128, 8><<<grid, tb>>>(x, W0, Nn, F0, F1, 0);
        k_gather<<<cdiv((long long)Nn * F4, 256), 256>>>(
            (const float4*)b0, (float4*)out, 0, Nn * F4, F4 - 1, lg);
    }

    // ---------- layer 2: relu(g_agg)[Nn,F1] @ W1 -> F2 in g_h; gather -> g_agg ----------
    {
        int F4 = F2 / 4, lg = (F4 == 32) ? 5 : 4;
        dim3 grid(F2 / 128, cdiv(Nn, GTM));
        k_gemm_t<128, 8><<<grid, tb>>>(nullptr, W1, Nn, F1, F2, 1);
        k_gather<<<cdiv((long long)Nn * F4, 256), 256>>>(
            (const float4*)b1, (float4*)out, 0, Nn * F4, F4 - 1, lg);
    }

    // ---------- layer 3: relu(g_agg)[Nn,F2] @ W2 -> F3 in g_h; gather -> d_out ----------
    {
        int F4 = F3 / 4, lg = (F4 == 32) ? 5 : 4;
        dim3 grid(F3 / 64, cdiv(Nn, GTM));
        k_gemm_t<64, 4><<<grid, tb>>>(nullptr, W2, Nn, F2, F3, 1);
        k_gather<<<cdiv((long long)Nn * F4, 256), 256>>>(
            (const float4*)b2, (float4*)out, 1, Nn * F4, F4 - 1, lg);
    }
    (void)n_in; (void)out_size;
}

// round 13
// speedup vs baseline: 1.2397x; 1.2397x over previous
#include <cuda_runtime.h>
#include <cuda_bf16.h>
#include <cstdint>

// Problem constants (fixed by the dataset)
#define MAX_N 50000
#define MAX_E 800000
#define MAX_F 128

// ---------------- scratch (static device globals) ----------------
__device__ __align__(16) int   g_degi[MAX_N];
__device__ __align__(16) float g_dinv[MAX_N];
__device__ __align__(16) int   g_rowptr[MAX_N + 1];
__device__ __align__(16) int   g_cursor[MAX_N];
__device__ __align__(16) int2  g_csr [MAX_E];     // .x = src, .y = bits(norm)
__device__ __align__(16) float g_h   [(size_t)MAX_N * MAX_F];
__device__ __align__(16) float g_agg [(size_t)MAX_N * MAX_F];
__device__ int g_is64;

// ---------------- dtype detection: int64 vs int32 edge_index ----------------
__global__ void k_detect(const int* __restrict__ ei32) {
    if (threadIdx.x || blockIdx.x) return;
    int is64 = 1;
    #pragma unroll 1
    for (int i = 0; i < 128; i++) {
        if (ei32[2 * i + 1] != 0) { is64 = 0; break; }
    }
    g_is64 = is64;
}

__device__ __forceinline__ int edge_id(const void* ei, size_t pos) {
    if (g_is64) return (int)((const long long*)ei)[pos];
    return ((const int*)ei)[pos];
}

// ---------------- degree / norm precompute ----------------
__global__ void k_zero_deg(int n) {
    int i = blockIdx.x * blockDim.x + threadIdx.x;
    if (i < n) g_degi[i] = 0;
}

__global__ void k_count_deg(const void* __restrict__ ei, int E) {
    int e = blockIdx.x * blockDim.x + threadIdx.x;
    if (e < E) atomicAdd(&g_degi[edge_id(ei, (size_t)E + e)], 1);
}

__global__ void k_dinv(int n) {
    int i = blockIdx.x * blockDim.x + threadIdx.x;
    if (i < n) g_dinv[i] = rsqrtf((float)g_degi[i] + 1.0f);
}

// ---------------- exclusive prefix scan of degrees -> row_ptr (single block) ----------------
__global__ __launch_bounds__(1024) void k_scan(int Nn) {
    __shared__ int warp_sums[32];
    __shared__ int carry_sh;
    int tid  = threadIdx.x;
    int lane = tid & 31;
    int wid  = tid >> 5;
    if (tid == 0) carry_sh = 0;
    __syncthreads();
    for (int base = 0; base < Nn; base += 1024) {
        int i = base + tid;
        int v = (i < Nn) ? g_degi[i] : 0;
        int s = v;
        #pragma unroll
        for (int o = 1; o < 32; o <<= 1) {
            int t = __shfl_up_sync(0xFFFFFFFFu, s, o);
            if (lane >= o) s += t;
        }
        if (lane == 31) warp_sums[wid] = s;
        __syncthreads();
        if (wid == 0) {
            int ws = warp_sums[lane];
            #pragma unroll
            for (int o = 1; o < 32; o <<= 1) {
                int t = __shfl_up_sync(0xFFFFFFFFu, ws, o);
                if (lane >= o) ws += t;
            }
            warp_sums[lane] = ws;   // inclusive over warps
        }
        __syncthreads();
        int warp_off = (wid == 0) ? 0 : warp_sums[wid - 1];
        int excl = carry_sh + warp_off + (s - v);
        if (i < Nn) { g_rowptr[i] = excl; g_cursor[i] = excl; }
        __syncthreads();
        if (tid == 0) carry_sh += warp_sums[31];
        __syncthreads();
    }
    if (tid == 0) g_rowptr[Nn] = carry_sh;
}

// ---------------- CSR build: one pass over edges -> counting-sorted CSR ----------------
__global__ void k_build(const void* __restrict__ ei, int E) {
    int e = blockIdx.x * blockDim.x + threadIdx.x;
    if (e >= E) return;
    int s = edge_id(ei, e);
    int d = edge_id(ei, (size_t)E + e);
    float nrm = g_dinv[s] * g_dinv[d];
    int pos = atomicAdd(&g_cursor[d], 1);
    int2 m;
    m.x = s;
    m.y = __float_as_int(nrm);
    g_csr[pos] = m;
}

// ---------------- GEMM (round-9 proven config): g_h[M,N] = act(A[M,K]) @ W[K,N] ----
// 128x64 tile, 256 threads, 8x4 per thread, K-step 16. N%64==0, K%16==0.
#define GTM 128
#define GTN 64
#define GTK 16

__global__ __launch_bounds__(256) void k_gemm(const float* __restrict__ Ax,
                                              const float* __restrict__ W,
                                              int M, int K, int N, int aSel) {
    __shared__ float As[GTK][GTM + 4];
    __shared__ float Bs[GTK][GTN + 4];
    const float* A = aSel ? (const float*)g_agg : Ax;
    int tx = threadIdx.x;            // 0..15 -> n
    int ty = threadIdx.y;            // 0..15 -> m (8 rows each)
    int tid = ty * 16 + tx;
    int row0 = blockIdx.y * GTM;
    int col0 = blockIdx.x * GTN;
    int K4 = K >> 2;

    float acc[8][4] = {};
    for (int k0 = 0; k0 < K; k0 += GTK) {
        // A tile: 128 rows x 16 k = 512 float4; 2 per thread
        #pragma unroll
        for (int i = 0; i < 2; i++) {
            int q  = tid * 2 + i;        // 0..511
            int m  = q >> 2;             // row in tile
            int kq = q & 3;              // which float4 along k
            int gm = row0 + m;
            float4 v = make_float4(0.f, 0.f, 0.f, 0.f);
            if (gm < M) v = ((const float4*)A)[(size_t)gm * K4 + (k0 >> 2) + kq];
            if (aSel) {
                v.x = fmaxf(v.x, 0.f); v.y = fmaxf(v.y, 0.f);
                v.z = fmaxf(v.z, 0.f); v.w = fmaxf(v.w, 0.f);
            }
            As[kq * 4 + 0][m] = v.x;
            As[kq * 4 + 1][m] = v.y;
            As[kq * 4 + 2][m] = v.z;
            As[kq * 4 + 3][m] = v.w;
        }
        // W tile: 16 k x 64 n = 256 float4; 1 per thread
        {
            int k  = tid >> 4;           // 0..15
            int nq = tid & 15;           // float4 within row
            float4 v = ((const float4*)W)[(size_t)(k0 + k) * (N >> 2) + (col0 >> 2) + nq];
            *(float4*)&Bs[k][nq * 4] = v;
        }
        __syncthreads();
        #pragma unroll
        for (int k = 0; k < GTK; k++) {
            float a[8], b[4];
            #pragma unroll
            for (int i = 0; i < 8; i++) a[i] = As[k][ty * 8 + i];
            #pragma unroll
            for (int j = 0; j < 4; j++) b[j] = Bs[k][tx * 4 + j];
            #pragma unroll
            for (int i = 0; i < 8; i++)
                #pragma unroll
                for (int j = 0; j < 4; j++)
                    acc[i][j] = fmaf(a[i], b[j], acc[i][j]);
        }
        __syncthreads();
    }
    #pragma unroll
    for (int i = 0; i < 8; i++) {
        int gm = row0 + ty * 8 + i;
        if (gm >= M) continue;
        float4 v = make_float4(acc[i][0], acc[i][1], acc[i][2], acc[i][3]);
        ((float4*)g_h)[((size_t)gm * N + col0) / 4 + tx] = v;
    }
}

// ---------------- CSR gather: dst[n,f] = b[f] + h[n,f]*dinv[n]^2 + sum_e h[src]*norm ----------------
__global__ void k_gather(const float4* __restrict__ bias, float4* __restrict__ outp,
                         int toOut, int total /* Nn*F4 */, int F4mask, int lg) {
    int t = blockIdx.x * blockDim.x + threadIdx.x;
    if (t >= total) return;
    int node = t >> lg;
    int f = t & F4mask;
    const float4* h4 = (const float4*)g_h;
    float d = g_dinv[node];
    float s0 = d * d;
    float4 acc = bias[f];
    float4 v = h4[((size_t)node << lg) + f];
    acc.x = fmaf(v.x, s0, acc.x);
    acc.y = fmaf(v.y, s0, acc.y);
    acc.z = fmaf(v.z, s0, acc.z);
    acc.w = fmaf(v.w, s0, acc.w);

    int p   = g_rowptr[node];
    int end = g_rowptr[node + 1];
    // unrolled by 4 for memory-level parallelism
    for (; p + 3 < end; p += 4) {
        int2 m0 = g_csr[p];
        int2 m1 = g_csr[p + 1];
        int2 m2 = g_csr[p + 2];
        int2 m3 = g_csr[p + 3];
        float4 v0 = h4[((size_t)m0.x << lg) + f];
        float4 v1 = h4[((size_t)m1.x << lg) + f];
        float4 v2 = h4[((size_t)m2.x << lg) + f];
        float4 v3 = h4[((size_t)m3.x << lg) + f];
        float s1 = __int_as_float(m0.y);
        float s2 = __int_as_float(m1.y);
        float s3 = __int_as_float(m2.y);
        float s4 = __int_as_float(m3.y);
        acc.x = fmaf(v0.x, s1, acc.x); acc.y = fmaf(v0.y, s1, acc.y);
        acc.z = fmaf(v0.z, s1, acc.z); acc.w = fmaf(v0.w, s1, acc.w);
        acc.x = fmaf(v1.x, s2, acc.x); acc.y = fmaf(v1.y, s2, acc.y);
        acc.z = fmaf(v1.z, s2, acc.z); acc.w = fmaf(v1.w, s2, acc.w);
        acc.x = fmaf(v2.x, s3, acc.x); acc.y = fmaf(v2.y, s3, acc.y);
        acc.z = fmaf(v2.z, s3, acc.z); acc.w = fmaf(v2.w, s3, acc.w);
        acc.x = fmaf(v3.x, s4, acc.x); acc.y = fmaf(v3.y, s4, acc.y);
        acc.z = fmaf(v3.z, s4, acc.z); acc.w = fmaf(v3.w, s4, acc.w);
    }
    for (; p < end; p++) {
        int2 m0 = g_csr[p];
        float s1 = __int_as_float(m0.y);
        float4 v0 = h4[((size_t)m0.x << lg) + f];
        acc.x = fmaf(v0.x, s1, acc.x); acc.y = fmaf(v0.y, s1, acc.y);
        acc.z = fmaf(v0.z, s1, acc.z); acc.w = fmaf(v0.w, s1, acc.w);
    }
    float4* dst = toOut ? outp : (float4*)g_agg;
    dst[t] = acc;
}

// ---------------- host launch (single stream, capture-safe) ----------------
static inline int cdiv(long long a, int b) { return (int)((a + b - 1) / b); }

extern "C" void kernel_launch(void* const* d_in, const int* in_sizes, int n_in,
                              void* d_out, int out_size) {
    const float* x  = (const float*)d_in[0];
    const void*  ei = d_in[1];                 // int32 OR int64 — detected on device
    const float* W0 = (const float*)d_in[2];
    const float* b0 = (const float*)d_in[3];
    const float* W1 = (const float*)d_in[4];
    const float* b1 = (const float*)d_in[5];
    const float* W2 = (const float*)d_in[6];
    const float* b2 = (const float*)d_in[7];
    float* out = (float*)d_out;

    int F1 = in_sizes[3];              // 128
    int F0 = in_sizes[2] / F1;         // 256
    int F2 = in_sizes[5];              // 128
    int F3 = in_sizes[7];              // 64
    int Nn = in_sizes[0] / F0;         // 50000
    int E  = in_sizes[1] / 2;          // 800000

    // 0) dtype detect; degrees; dinv; scan; fused CSR build (one edge pass)
    k_detect    <<<1, 32>>>((const int*)ei);
    k_zero_deg  <<<cdiv(Nn, 256), 256>>>(Nn);
    k_count_deg <<<cdiv(E, 256), 256>>>(ei, E);
    k_dinv      <<<cdiv(Nn, 256), 256>>>(Nn);
    k_scan      <<<1, 1024>>>(Nn);
    k_build     <<<cdiv(E, 256), 256>>>(ei, E);

    dim3 tb(16, 16);

    // ---------- layer 1: x[Nn,F0] @ W0 -> F1 in g_h; gather -> g_agg ----------
    {
        int F4 = F1 / 4, lg = (F4 == 32) ? 5 : 4;
        dim3 grid(F1 / GTN, cdiv(Nn, GTM));
        k_gemm<<<grid, tb>>>(x, W0, Nn, F0, F1, 0);
        k_gather<<<cdiv((long long)Nn * F4, 256), 256>>>(
            (const float4*)b0, (float4*)out, 0, Nn * F4, F4 - 1, lg);
    }

    // ---------- layer 2: relu(g_agg)[Nn,F1] @ W1 -> F2 in g_h; gather -> g_agg ----------
    {
        int F4 = F2 / 4, lg = (F4 == 32) ? 5 : 4;
        dim3 grid(F2 / GTN, cdiv(Nn, GTM));
        k_gemm<<<grid, tb>>>(nullptr, W1, Nn, F1, F2, 1);
        k_gather<<<cdiv((long long)Nn * F4, 256), 256>>>(
            (const float4*)b1, (float4*)out, 0, Nn * F4, F4 - 1, lg);
    }

    // ---------- layer 3: relu(g_agg)[Nn,F2] @ W2 -> F3 in g_h; gather -> d_out ----------
    {
        int F4 = F3 / 4, lg = (F4 == 32) ? 5 : 4;
        dim3 grid(F3 / GTN, cdiv(Nn, GTM));
        k_gemm<<<grid, tb>>>(nullptr, W2, Nn, F2, F3, 1);
        k_gather<<<cdiv((long long)Nn * F4, 256), 256>>>(
            (const float4*)b2, (float4*)out, 1, Nn * F4, F4 - 1, lg);
    }
    (void)n_in; (void)out_size;
}

// round 14
// speedup vs baseline: 1.4288x; 1.1525x over previous
#include <cuda_runtime.h>
#include <cuda_bf16.h>
#include <mma.h>
#include <cstdint>

using namespace nvcuda;

// Problem constants (fixed by the dataset)
#define MAX_N 50000
#define MAX_E 800000
#define MAX_F 128

// GEMM tiling
#define WTM 128            // block tile M
#define WTN 64             // block tile N
#define WKC 32             // K chunk
#define ALD 48             // A smem row stride (elements, mult of 16)
#define BLD 80             // B smem row stride (elements, mult of 16)

// ---------------- scratch (static device globals) ----------------
__device__ __align__(16) int   g_degi[MAX_N];
__device__ __align__(16) float g_dinv[MAX_N];
__device__ __align__(16) int   g_rowptr[MAX_N + 1];
__device__ __align__(16) int   g_cursor[MAX_N];
__device__ __align__(16) int2  g_csr [MAX_E];     // .x = src, .y = bits(norm)
// g_h padded by one M-tile of rows: unguarded wmma stores of the last partial
// tile land in scratch pad, never beyond this array.
__device__ __align__(16) float g_h   [(size_t)(MAX_N + WTM) * MAX_F];
__device__ __align__(16) float g_agg [(size_t)MAX_N * MAX_F];
__device__ int g_is64;

// ---------------- dtype detection: int64 vs int32 edge_index ----------------
__global__ void k_detect(const int* __restrict__ ei32) {
    if (threadIdx.x || blockIdx.x) return;
    int is64 = 1;
    #pragma unroll 1
    for (int i = 0; i < 128; i++) {
        if (ei32[2 * i + 1] != 0) { is64 = 0; break; }
    }
    g_is64 = is64;
}

__device__ __forceinline__ int edge_id(const void* ei, size_t pos) {
    if (g_is64) return (int)((const long long*)ei)[pos];
    return ((const int*)ei)[pos];
}

// ---------------- degree / norm precompute ----------------
__global__ void k_zero_deg(int n) {
    int i = blockIdx.x * blockDim.x + threadIdx.x;
    if (i < n) g_degi[i] = 0;
}

__global__ void k_count_deg(const void* __restrict__ ei, int E) {
    int e = blockIdx.x * blockDim.x + threadIdx.x;
    if (e < E) atomicAdd(&g_degi[edge_id(ei, (size_t)E + e)], 1);
}

__global__ void k_dinv(int n) {
    int i = blockIdx.x * blockDim.x + threadIdx.x;
    if (i < n) g_dinv[i] = rsqrtf((float)g_degi[i] + 1.0f);
}

// ---------------- exclusive prefix scan of degrees -> row_ptr (single block) ----------------
__global__ __launch_bounds__(1024) void k_scan(int Nn) {
    __shared__ int warp_sums[32];
    __shared__ int carry_sh;
    int tid  = threadIdx.x;
    int lane = tid & 31;
    int wid  = tid >> 5;
    if (tid == 0) carry_sh = 0;
    __syncthreads();
    for (int base = 0; base < Nn; base += 1024) {
        int i = base + tid;
        int v = (i < Nn) ? g_degi[i] : 0;
        int s = v;
        #pragma unroll
        for (int o = 1; o < 32; o <<= 1) {
            int t = __shfl_up_sync(0xFFFFFFFFu, s, o);
            if (lane >= o) s += t;
        }
        if (lane == 31) warp_sums[wid] = s;
        __syncthreads();
        if (wid == 0) {
            int ws = warp_sums[lane];
            #pragma unroll
            for (int o = 1; o < 32; o <<= 1) {
                int t = __shfl_up_sync(0xFFFFFFFFu, ws, o);
                if (lane >= o) ws += t;
            }
            warp_sums[lane] = ws;   // inclusive over warps
        }
        __syncthreads();
        int warp_off = (wid == 0) ? 0 : warp_sums[wid - 1];
        int excl = carry_sh + warp_off + (s - v);
        if (i < Nn) { g_rowptr[i] = excl; g_cursor[i] = excl; }
        __syncthreads();
        if (tid == 0) carry_sh += warp_sums[31];
        __syncthreads();
    }
    if (tid == 0) g_rowptr[Nn] = carry_sh;
}

// ---------------- CSR build: one pass over edges -> counting-sorted CSR ----------------
__global__ void k_build(const void* __restrict__ ei, int E) {
    int e = blockIdx.x * blockDim.x + threadIdx.x;
    if (e >= E) return;
    int s = edge_id(ei, e);
    int d = edge_id(ei, (size_t)E + e);
    float nrm = g_dinv[s] * g_dinv[d];
    int pos = atomicAdd(&g_cursor[d], 1);
    int2 m;
    m.x = s;
    m.y = __float_as_int(nrm);
    g_csr[pos] = m;
}

// ---------------- GEMM: g_h[M,N] = act(A[M,K]) @ W[K,N], split-bf16 tensor cores ----
// a = hi + lo (bf16 split); acc += hi*Whi + hi*Wlo + lo*Whi in fp32.
// Block: 256 threads = 8 warps (4x2), warp computes 32x32 via 2x2 wmma frags.
__global__ __launch_bounds__(256) void k_gemm(const float* __restrict__ Ax,
                                              const float* __restrict__ W,
                                              int M, int K, int N, int aSel) {
    __shared__ __nv_bfloat16 Ah[WTM][ALD];
    __shared__ __nv_bfloat16 Al[WTM][ALD];
    __shared__ __nv_bfloat16 Bh[WKC][BLD];
    __shared__ __nv_bfloat16 Bl[WKC][BLD];
    const float* A = aSel ? (const float*)g_agg : Ax;
    int tid  = threadIdx.x;
    int warp = tid >> 5;
    int wm   = warp >> 1;            // 0..3 -> M sub-tile
    int wn   = warp & 1;             // 0..1 -> N sub-tile
    int row0 = blockIdx.y * WTM;
    int col0 = blockIdx.x * WTN;
    int K4   = K >> 2;

    wmma::fragment<wmma::accumulator, 16, 16, 16, float> acc[2][2];
    #pragma unroll
    for (int i = 0; i < 2; i++)
        #pragma unroll
        for (int j = 0; j < 2; j++)
            wmma::fill_fragment(acc[i][j], 0.0f);

    for (int k0 = 0; k0 < K; k0 += WKC) {
        // A tile: 128 rows x 32 k = 1024 float4; 4 per thread
        #pragma unroll
        for (int i = 0; i < 4; i++) {
            int q  = tid + i * 256;      // 0..1023
            int m  = q >> 3;             // row in tile
            int kq = q & 7;              // float4 index along k
            int gm = row0 + m;
            float4 v = make_float4(0.f, 0.f, 0.f, 0.f);
            if (gm < M) v = ((const float4*)A)[(size_t)gm * K4 + (k0 >> 2) + kq];
            if (aSel) {
                v.x = fmaxf(v.x, 0.f); v.y = fmaxf(v.y, 0.f);
                v.z = fmaxf(v.z, 0.f); v.w = fmaxf(v.w, 0.f);
            }
            float vv[4] = {v.x, v.y, v.z, v.w};
            #pragma unroll
            for (int c = 0; c < 4; c++) {
                __nv_bfloat16 h = __float2bfloat16(vv[c]);
                float r = vv[c] - __bfloat162float(h);
                Ah[m][kq * 4 + c] = h;
                Al[m][kq * 4 + c] = __float2bfloat16(r);
            }
        }
        // B tile: 32 k x 64 n = 512 float4; 2 per thread
        #pragma unroll
        for (int i = 0; i < 2; i++) {
            int q  = tid + i * 256;      // 0..511
            int k  = q >> 4;             // 0..31
            int nq = q & 15;             // float4 along n
            float4 v = ((const float4*)W)[(size_t)(k0 + k) * (N >> 2) + (col0 >> 2) + nq];
            float vv[4] = {v.x, v.y, v.z, v.w};
            #pragma unroll
            for (int c = 0; c < 4; c++) {
                __nv_bfloat16 h = __float2bfloat16(vv[c]);
                float r = vv[c] - __bfloat162float(h);
                Bh[k][nq * 4 + c] = h;
                Bl[k][nq * 4 + c] = __float2bfloat16(r);
            }
        }
        __syncthreads();
        #pragma unroll
        for (int kk = 0; kk < WKC; kk += 16) {
            wmma::fragment<wmma::matrix_a, 16, 16, 16, __nv_bfloat16, wmma::row_major> ah[2], al[2];
            wmma::fragment<wmma::matrix_b, 16, 16, 16, __nv_bfloat16, wmma::row_major> bh[2], bl[2];
            #pragma unroll
            for (int i = 0; i < 2; i++) {
                wmma::load_matrix_sync(ah[i], &Ah[wm * 32 + i * 16][kk], ALD);
                wmma::load_matrix_sync(al[i], &Al[wm * 32 + i * 16][kk], ALD);
            }
            #pragma unroll
            for (int j = 0; j < 2; j++) {
                wmma::load_matrix_sync(bh[j], &Bh[kk][wn * 32 + j * 16], BLD);
                wmma::load_matrix_sync(bl[j], &Bl[kk][wn * 32 + j * 16], BLD);
            }
            #pragma unroll
            for (int i = 0; i < 2; i++)
                #pragma unroll
                for (int j = 0; j < 2; j++) {
                    wmma::mma_sync(acc[i][j], ah[i], bh[j], acc[i][j]);
                    wmma::mma_sync(acc[i][j], ah[i], bl[j], acc[i][j]);
                    wmma::mma_sync(acc[i][j], al[i], bh[j], acc[i][j]);
                }
        }
        __syncthreads();
    }
    #pragma unroll
    for (int i = 0; i < 2; i++) {
        int gm = row0 + wm * 32 + i * 16;   // may overrun into g_h pad rows (safe)
        #pragma unroll
        for (int j = 0; j < 2; j++)
            wmma::store_matrix_sync(&g_h[(size_t)gm * N + col0 + wn * 32 + j * 16],
                                    acc[i][j], N, wmma::mem_row_major);
    }
}

// ---------------- CSR gather: dst[n,f] = b[f] + h[n,f]*dinv[n]^2 + sum_e h[src]*norm ----------------
__global__ void k_gather(const float4* __restrict__ bias, float4* __restrict__ outp,
                         int toOut, int total /* Nn*F4 */, int F4mask, int lg) {
    int t = blockIdx.x * blockDim.x + threadIdx.x;
    if (t >= total) return;
    int node = t >> lg;
    int f = t & F4mask;
    const float4* h4 = (const float4*)g_h;
    float d = g_dinv[node];
    float s0 = d * d;
    float4 acc = bias[f];
    float4 v = h4[((size_t)node << lg) + f];
    acc.x = fmaf(v.x, s0, acc.x);
    acc.y = fmaf(v.y, s0, acc.y);
    acc.z = fmaf(v.z, s0, acc.z);
    acc.w = fmaf(v.w, s0, acc.w);

    int p   = g_rowptr[node];
    int end = g_rowptr[node + 1];
    // unrolled by 4 for memory-level parallelism
    for (; p + 3 < end; p += 4) {
        int2 m0 = g_csr[p];
        int2 m1 = g_csr[p + 1];
        int2 m2 = g_csr[p + 2];
        int2 m3 = g_csr[p + 3];
        float4 v0 = h4[((size_t)m0.x << lg) + f];
        float4 v1 = h4[((size_t)m1.x << lg) + f];
        float4 v2 = h4[((size_t)m2.x << lg) + f];
        float4 v3 = h4[((size_t)m3.x << lg) + f];
        float s1 = __int_as_float(m0.y);
        float s2 = __int_as_float(m1.y);
        float s3 = __int_as_float(m2.y);
        float s4 = __int_as_float(m3.y);
        acc.x = fmaf(v0.x, s1, acc.x); acc.y = fmaf(v0.y, s1, acc.y);
        acc.z = fmaf(v0.z, s1, acc.z); acc.w = fmaf(v0.w, s1, acc.w);
        acc.x = fmaf(v1.x, s2, acc.x); acc.y = fmaf(v1.y, s2, acc.y);
        acc.z = fmaf(v1.z, s2, acc.z); acc.w = fmaf(v1.w, s2, acc.w);
        acc.x = fmaf(v2.x, s3, acc.x); acc.y = fmaf(v2.y, s3, acc.y);
        acc.z = fmaf(v2.z, s3, acc.z); acc.w = fmaf(v2.w, s3, acc.w);
        acc.x = fmaf(v3.x, s4, acc.x); acc.y = fmaf(v3.y, s4, acc.y);
        acc.z = fmaf(v3.z, s4, acc.z); acc.w = fmaf(v3.w, s4, acc.w);
    }
    for (; p < end; p++) {
        int2 m0 = g_csr[p];
        float s1 = __int_as_float(m0.y);
        float4 v0 = h4[((size_t)m0.x << lg) + f];
        acc.x = fmaf(v0.x, s1, acc.x); acc.y = fmaf(v0.y, s1, acc.y);
        acc.z = fmaf(v0.z, s1, acc.z); acc.w = fmaf(v0.w, s1, acc.w);
    }
    float4* dst = toOut ? outp : (float4*)g_agg;
    dst[t] = acc;
}

// ---------------- host launch (single stream, capture-safe) ----------------
static inline int cdiv(long long a, int b) { return (int)((a + b - 1) / b); }

extern "C" void kernel_launch(void* const* d_in, const int* in_sizes, int n_in,
                              void* d_out, int out_size) {
    const float* x  = (const float*)d_in[0];
    const void*  ei = d_in[1];                 // int32 OR int64 — detected on device
    const float* W0 = (const float*)d_in[2];
    const float* b0 = (const float*)d_in[3];
    const float* W1 = (const float*)d_in[4];
    const float* b1 = (const float*)d_in[5];
    const float* W2 = (const float*)d_in[6];
    const float* b2 = (const float*)d_in[7];
    float* out = (float*)d_out;

    int F1 = in_sizes[3];              // 128
    int F0 = in_sizes[2] / F1;         // 256
    int F2 = in_sizes[5];              // 128
    int F3 = in_sizes[7];              // 64
    int Nn = in_sizes[0] / F0;         // 50000
    int E  = in_sizes[1] / 2;          // 800000

    // 0) dtype detect; degrees; dinv; scan; fused CSR build (one edge pass)
    k_detect    <<<1, 32>>>((const int*)ei);
    k_zero_deg  <<<cdiv(Nn, 256), 256>>>(Nn);
    k_count_deg <<<cdiv(E, 256), 256>>>(ei, E);
    k_dinv      <<<cdiv(Nn, 256), 256>>>(Nn);
    k_scan      <<<1, 1024>>>(Nn);
    k_build     <<<cdiv(E, 256), 256>>>(ei, E);

    // ---------- layer 1: x[Nn,F0] @ W0 -> F1 in g_h; gather -> g_agg ----------
    {
        int F4 = F1 / 4, lg = (F4 == 32) ? 5 : 4;
        dim3 grid(F1 / WTN, cdiv(Nn, WTM));
        k_gemm<<<grid, 256>>>(x, W0, Nn, F0, F1, 0);
        k_gather<<<cdiv((long long)Nn * F4, 256), 256>>>(
            (const float4*)b0, (float4*)out, 0, Nn * F4, F4 - 1, lg);
    }

    // ---------- layer 2: relu(g_agg)[Nn,F1] @ W1 -> F2 in g_h; gather -> g_agg ----------
    {
        int F4 = F2 / 4, lg = (F4 == 32) ? 5 : 4;
        dim3 grid(F2 / WTN, cdiv(Nn, WTM));
        k_gemm<<<grid, 256>>>(nullptr, W1, Nn, F1, F2, 1);
        k_gather<<<cdiv((long long)Nn * F4, 256), 256>>>(
            (const float4*)b1, (float4*)out, 0, Nn * F4, F4 - 1, lg);
    }

    // ---------- layer 3: relu(g_agg)[Nn,F2] @ W2 -> F3 in g_h; gather -> d_out ----------
    {
        int F4 = F3 / 4, lg = (F4 == 32) ? 5 : 4;
        dim3 grid(F3 / WTN, cdiv(Nn, WTM));
        k_gemm<<<grid, 256>>>(nullptr, W2, Nn, F2, F3, 1);
        k_gather<<<cdiv((long long)Nn * F4, 256), 256>>>(
            (const float4*)b2, (float4*)out, 1, Nn * F4, F4 - 1, lg);
    }
    (void)n_in; (void)out_size;
}